// round 8
// baseline (speedup 1.0000x reference)
#include <cuda_runtime.h>
#include <cuda_bf16.h>

#define PH 7
#define PW 7
#define C_ 256
#define H_ 40
#define W_ 40
#define NMAX 64

// f32(1/7) and f32(1/3) as XLA's constant-folded reciprocals.
#define RECIP7_BITS 0x3E124925u
#define RECIP3_BITS 0x3EAAAAABu

__device__ float g_cat_rois[4096 * 5];

__constant__ int c_sel[8] = {0, 1, 2, 3, 5, 6, 7, 8};

__device__ __forceinline__ float decode_scalar(const void* p, float dflt)
{
    if (p == nullptr) return dflt;
    unsigned int lo = *(const unsigned int*)p;
    if (lo >= 1u && lo <= 1000000u) return (float)lo;   // int32/int64 low word
    float f = __uint_as_float(lo);
    if (f >= 1.0f && f <= 1.0e6f) return f;             // float32
    return dflt;
}

// ---------------------------------------------------------------------------
// Stage 1: context anchors + IoU relabel (one block, N*8 threads).
// ---------------------------------------------------------------------------
__global__ void anchor_kernel(const float* __restrict__ rois,
                              const void* __restrict__ hh_p,
                              const void* __restrict__ hw_p,
                              float* __restrict__ out_tail,
                              int N)
{
    __shared__ float R5[NMAX][5];
    __shared__ float GT[NMAX * 8][4];

    int t = threadIdx.x;
    int total = N * 8;
    for (int k = t; k < N * 5; k += total) R5[k / 5][k % 5] = rois[k];
    __syncthreads();

    float fhh = decode_scalar(hh_p, 640.0f);
    float fhw = decode_scalar(hw_p, 640.0f);

    int n  = t / 8;
    int jj = t % 8;
    int m  = c_sel[jj];
    float ky = (float)(m / 3);
    float kx = (float)(m % 3);

    float x1 = R5[n][1], y1 = R5[n][2], x2 = R5[n][3], y2 = R5[n][4];
    float w = __fsub_rn(x2, x1), h = __fsub_rn(y2, y1);

    float cx = __fadd_rn(x1, __fmul_rn(w, __fsub_rn(kx, 0.5f)));
    float cy = __fadd_rn(y1, __fmul_rn(h, __fsub_rn(ky, 0.5f)));
    float w4 = __fmul_rn(w, 0.25f);   // /4: power of two, recip exact
    float h4 = __fmul_rn(h, 0.25f);
    float b0 = __fsub_rn(cx, w4), b1 = __fsub_rn(cy, h4);
    float b2 = __fadd_rn(cx, w4), b3 = __fadd_rn(cy, h4);
    float bw = __fadd_rn(__fsub_rn(b2, b0), 1.0f);
    float bh = __fadd_rn(__fsub_rn(b3, b1), 1.0f);
    bool invalid = (b0 < 0.0f) || (b1 < 0.0f) || (b2 >= fhw) || (b3 >= fhh)
                || (bw < 16.0f) || (bh < 16.0f);
    if (invalid) { b0 = x1; b1 = y1; b2 = x2; b3 = y2; }
    GT[t][0] = b0; GT[t][1] = b1; GT[t][2] = b2; GT[t][3] = b3;
    __syncthreads();

    float g0 = GT[t][0], g1 = GT[t][1], g2 = GT[t][2], g3 = GT[t][3];
    float gwp = __fadd_rn(__fsub_rn(g2, g0), 1.0f);
    float ghp = __fadd_rn(__fsub_rn(g3, g1), 1.0f);
    float gArea = __fmul_rn(gwp, ghp);

    float gt_max = -1.0e38f;
    int best = 0;
    for (int a = 0; a < N; a++) {
        float a0 = R5[a][1], a1 = R5[a][2], a2 = R5[a][3], a3 = R5[a][4];
        float aw = __fadd_rn(__fsub_rn(a2, a0), 1.0f);
        float ah = __fadd_rn(__fsub_rn(a3, a1), 1.0f);
        float iw = fmaxf(__fadd_rn(__fsub_rn(fminf(a2, g2), fmaxf(a0, g0)), 1.0f), 0.0f);
        float ih = fmaxf(__fadd_rn(__fsub_rn(fminf(a3, g3), fmaxf(a1, g1)), 1.0f), 0.0f);
        float inter = __fmul_rn(iw, ih);
        float uni = __fsub_rn(__fadd_rn(__fmul_rn(aw, ah), gArea), inter);
        float ov = __fdiv_rn(inter, uni);   // non-constant divisor: stays a real divide
        if (gwp == 1.0f && ghp == 1.0f) ov = 0.0f;
        if (aw == 1.0f && ah == 1.0f)   ov = -1.0f;
        if (ov > gt_max) { gt_max = ov; best = a; }
    }

    bool lab = (gt_max >= 0.3f);
    float w_cell = __fsub_rn(g2, g0);
    float h_cell = __fsub_rn(g3, g1);
    float rw = lab ? __fsub_rn(R5[best][3], R5[best][1]) : 0.0f;
    float rh = lab ? __fsub_rn(R5[best][4], R5[best][2]) : 0.0f;
    bool kill1 = (fmaxf(rw, rh) >= fmaxf(w_cell, h_cell));
    // /3 via XLA-style reciprocal multiply
    float third = __fmul_rn(fminf(w_cell, h_cell), __uint_as_float(RECIP3_BITS));
    bool kill2 = (fminf(rw, rh) < third);
    lab = lab && (!kill1) && (!kill2);

    float o1, o2, o3, o4;
    if (lab) { o1 = R5[best][1]; o2 = R5[best][2]; o3 = R5[best][3]; o4 = R5[best][4]; }
    else     { o1 = g0; o2 = g1; o3 = g2; o4 = g3; }

    int row = n * 9 + jj + 1;
    g_cat_rois[row * 5 + 0] = 0.0f;
    g_cat_rois[row * 5 + 1] = o1;
    g_cat_rois[row * 5 + 2] = o2;
    g_cat_rois[row * 5 + 3] = o3;
    g_cat_rois[row * 5 + 4] = o4;
    if (out_tail) {
        out_tail[row * 5 + 0] = 0.0f;
        out_tail[row * 5 + 1] = o1;
        out_tail[row * 5 + 2] = o2;
        out_tail[row * 5 + 3] = o3;
        out_tail[row * 5 + 4] = o4;
    }

    if (t < N) {
        int rr = t * 9;
        #pragma unroll
        for (int k = 0; k < 5; k++) {
            float v = R5[t][k];
            g_cat_rois[rr * 5 + k] = v;
            if (out_tail) out_tail[rr * 5 + k] = v;
        }
    }
}

// ---------------------------------------------------------------------------
// Stage 2: Caffe max RoIPool, fast int-window form (bit-equivalent to the
// literal mask form), with XLA-style bsh/bsw = size * (1/7).
// ---------------------------------------------------------------------------
__global__ void pool_kernel(const float* __restrict__ feat,
                            float* __restrict__ out, int total)
{
    int idx = blockIdx.x * blockDim.x + threadIdx.x;
    if (idx >= total) return;

    int j = idx % PW;
    int i = (idx / PW) % PH;
    int c = (idx / (PW * PH)) % C_;
    int b = idx / (PW * PH * C_);

    float x1 = g_cat_rois[b * 5 + 1];
    float y1 = g_cat_rois[b * 5 + 2];
    float x2 = g_cat_rois[b * 5 + 3];
    float y2 = g_cat_rois[b * 5 + 4];

    float sw = rintf(__fmul_rn(x1, 0.0625f));
    float sh = rintf(__fmul_rn(y1, 0.0625f));
    float ew = rintf(__fmul_rn(x2, 0.0625f));
    float eh = rintf(__fmul_rn(y2, 0.0625f));

    const float r7 = __uint_as_float(RECIP7_BITS);
    float bsh = __fmul_rn(fmaxf(__fadd_rn(__fsub_rn(eh, sh), 1.0f), 1.0f), r7);
    float bsw = __fmul_rn(fmaxf(__fadd_rn(__fsub_rn(ew, sw), 1.0f), 1.0f), r7);

    float hsf = fminf(fmaxf(__fadd_rn(floorf(__fmul_rn((float)i, bsh)), sh), 0.0f), 40.0f);
    float hef = fminf(fmaxf(__fadd_rn(ceilf(__fmul_rn((float)(i + 1), bsh)), sh), 0.0f), 40.0f);
    float wsf = fminf(fmaxf(__fadd_rn(floorf(__fmul_rn((float)j, bsw)), sw), 0.0f), 40.0f);
    float wef = fminf(fmaxf(__fadd_rn(ceilf(__fmul_rn((float)(j + 1), bsw)), sw), 0.0f), 40.0f);

    int hs = (int)hsf, he = (int)hef, ws = (int)wsf, we = (int)wef;

    float v = 0.0f;
    if (he > hs && we > ws) {
        float mmax = -1.0e30f;
        const float* fc = feat + c * (H_ * W_);
        for (int hy = hs; hy < he; ++hy) {
            const float* frow = fc + hy * W_;
            for (int wx = ws; wx < we; ++wx)
                mmax = fmaxf(mmax, __ldg(&frow[wx]));
        }
        v = mmax;
    }
    out[idx] = v;
}

// ---------------------------------------------------------------------------
extern "C" void kernel_launch(void* const* d_in, const int* in_sizes, int n_in,
                              void* d_out, int out_size)
{
    const float* features = (const float*)d_in[0];
    const float* rois     = (const float*)d_in[1];
    const void*  hh_p     = (n_in > 2) ? d_in[2] : nullptr;
    const void*  hw_p     = (n_in > 3) ? d_in[3] : nullptr;

    int N = in_sizes[1] / 5;              // 32
    int NB = N * 9;                       // 288
    int pool_total = NB * C_ * PH * PW;   // 3,612,672

    float* out = (float*)d_out;
    float* out_tail = (out_size >= pool_total + NB * 5) ? (out + pool_total) : nullptr;

    int threads1 = N * 8;
    anchor_kernel<<<1, threads1>>>(rois, hh_p, hw_p, out_tail, N);

    int write_total = pool_total < out_size ? pool_total : out_size;
    int threads2 = 256;
    int blocks2 = (write_total + threads2 - 1) / threads2;
    pool_kernel<<<blocks2, threads2>>>(features, out, write_total);
}

// round 11
// speedup vs baseline: 1.5014x; 1.5014x over previous
#include <cuda_runtime.h>
#include <cuda_bf16.h>

#define PH 7
#define PW 7
#define C_ 256
#define H_ 40
#define W_ 40
#define NMAX 64
#define CCHUNK 8                      // channels per block
#define POOL_THREADS (PH * PW * CCHUNK)   // 392

// f32(1/7) and f32(1/3) as XLA's constant-folded reciprocals.
#define RECIP7_BITS 0x3E124925u
#define RECIP3_BITS 0x3EAAAAABu

__device__ float g_cat_rois[4096 * 5];

__constant__ int c_sel[8] = {0, 1, 2, 3, 5, 6, 7, 8};

__device__ __forceinline__ float decode_scalar(const void* p, float dflt)
{
    if (p == nullptr) return dflt;
    unsigned int lo = *(const unsigned int*)p;
    if (lo >= 1u && lo <= 1000000u) return (float)lo;   // int32/int64 low word
    float f = __uint_as_float(lo);
    if (f >= 1.0f && f <= 1.0e6f) return f;             // float32
    return dflt;
}

// ---------------------------------------------------------------------------
// Stage 1: context anchors + IoU relabel (one block, N*8 threads). Unchanged
// from the passing R8 kernel.
// ---------------------------------------------------------------------------
__global__ void anchor_kernel(const float* __restrict__ rois,
                              const void* __restrict__ hh_p,
                              const void* __restrict__ hw_p,
                              float* __restrict__ out_tail,
                              int N)
{
    __shared__ float R5[NMAX][5];
    __shared__ float GT[NMAX * 8][4];

    int t = threadIdx.x;
    int total = N * 8;
    for (int k = t; k < N * 5; k += total) R5[k / 5][k % 5] = rois[k];
    __syncthreads();

    float fhh = decode_scalar(hh_p, 640.0f);
    float fhw = decode_scalar(hw_p, 640.0f);

    int n  = t / 8;
    int jj = t % 8;
    int m  = c_sel[jj];
    float ky = (float)(m / 3);
    float kx = (float)(m % 3);

    float x1 = R5[n][1], y1 = R5[n][2], x2 = R5[n][3], y2 = R5[n][4];
    float w = __fsub_rn(x2, x1), h = __fsub_rn(y2, y1);

    float cx = __fadd_rn(x1, __fmul_rn(w, __fsub_rn(kx, 0.5f)));
    float cy = __fadd_rn(y1, __fmul_rn(h, __fsub_rn(ky, 0.5f)));
    float w4 = __fmul_rn(w, 0.25f);
    float h4 = __fmul_rn(h, 0.25f);
    float b0 = __fsub_rn(cx, w4), b1 = __fsub_rn(cy, h4);
    float b2 = __fadd_rn(cx, w4), b3 = __fadd_rn(cy, h4);
    float bw = __fadd_rn(__fsub_rn(b2, b0), 1.0f);
    float bh = __fadd_rn(__fsub_rn(b3, b1), 1.0f);
    bool invalid = (b0 < 0.0f) || (b1 < 0.0f) || (b2 >= fhw) || (b3 >= fhh)
                || (bw < 16.0f) || (bh < 16.0f);
    if (invalid) { b0 = x1; b1 = y1; b2 = x2; b3 = y2; }
    GT[t][0] = b0; GT[t][1] = b1; GT[t][2] = b2; GT[t][3] = b3;
    __syncthreads();

    float g0 = GT[t][0], g1 = GT[t][1], g2 = GT[t][2], g3 = GT[t][3];
    float gwp = __fadd_rn(__fsub_rn(g2, g0), 1.0f);
    float ghp = __fadd_rn(__fsub_rn(g3, g1), 1.0f);
    float gArea = __fmul_rn(gwp, ghp);

    float gt_max = -1.0e38f;
    int best = 0;
    for (int a = 0; a < N; a++) {
        float a0 = R5[a][1], a1 = R5[a][2], a2 = R5[a][3], a3 = R5[a][4];
        float aw = __fadd_rn(__fsub_rn(a2, a0), 1.0f);
        float ah = __fadd_rn(__fsub_rn(a3, a1), 1.0f);
        float iw = fmaxf(__fadd_rn(__fsub_rn(fminf(a2, g2), fmaxf(a0, g0)), 1.0f), 0.0f);
        float ih = fmaxf(__fadd_rn(__fsub_rn(fminf(a3, g3), fmaxf(a1, g1)), 1.0f), 0.0f);
        float inter = __fmul_rn(iw, ih);
        float uni = __fsub_rn(__fadd_rn(__fmul_rn(aw, ah), gArea), inter);
        float ov = __fdiv_rn(inter, uni);
        if (gwp == 1.0f && ghp == 1.0f) ov = 0.0f;
        if (aw == 1.0f && ah == 1.0f)   ov = -1.0f;
        if (ov > gt_max) { gt_max = ov; best = a; }
    }

    bool lab = (gt_max >= 0.3f);
    float w_cell = __fsub_rn(g2, g0);
    float h_cell = __fsub_rn(g3, g1);
    float rw = lab ? __fsub_rn(R5[best][3], R5[best][1]) : 0.0f;
    float rh = lab ? __fsub_rn(R5[best][4], R5[best][2]) : 0.0f;
    bool kill1 = (fmaxf(rw, rh) >= fmaxf(w_cell, h_cell));
    float third = __fmul_rn(fminf(w_cell, h_cell), __uint_as_float(RECIP3_BITS));
    bool kill2 = (fminf(rw, rh) < third);
    lab = lab && (!kill1) && (!kill2);

    float o1, o2, o3, o4;
    if (lab) { o1 = R5[best][1]; o2 = R5[best][2]; o3 = R5[best][3]; o4 = R5[best][4]; }
    else     { o1 = g0; o2 = g1; o3 = g2; o4 = g3; }

    int row = n * 9 + jj + 1;
    g_cat_rois[row * 5 + 0] = 0.0f;
    g_cat_rois[row * 5 + 1] = o1;
    g_cat_rois[row * 5 + 2] = o2;
    g_cat_rois[row * 5 + 3] = o3;
    g_cat_rois[row * 5 + 4] = o4;
    if (out_tail) {
        out_tail[row * 5 + 0] = 0.0f;
        out_tail[row * 5 + 1] = o1;
        out_tail[row * 5 + 2] = o2;
        out_tail[row * 5 + 3] = o3;
        out_tail[row * 5 + 4] = o4;
    }

    if (t < N) {
        int rr = t * 9;
        #pragma unroll
        for (int k = 0; k < 5; k++) {
            float v = R5[t][k];
            g_cat_rois[rr * 5 + k] = v;
            if (out_tail) out_tail[rr * 5 + k] = v;
        }
    }
}

// ---------------------------------------------------------------------------
// Stage 2: pool. One block per (box, 8-channel chunk). First 49 threads
// compute the 49 bin windows into smem (bit-identical math to R8); all 392
// threads then do the short max loop + one coalesced store each.
// ---------------------------------------------------------------------------
__global__ void __launch_bounds__(POOL_THREADS)
pool_kernel(const float* __restrict__ feat, float* __restrict__ out)
{
    __shared__ int s_hs[49], s_he[49], s_ws[49], s_we[49];

    int b = blockIdx.x;
    int t = threadIdx.x;

    if (t < 49) {
        int i = t / 7, j = t % 7;

        float x1 = g_cat_rois[b * 5 + 1];
        float y1 = g_cat_rois[b * 5 + 2];
        float x2 = g_cat_rois[b * 5 + 3];
        float y2 = g_cat_rois[b * 5 + 4];

        float sw = rintf(__fmul_rn(x1, 0.0625f));
        float sh = rintf(__fmul_rn(y1, 0.0625f));
        float ew = rintf(__fmul_rn(x2, 0.0625f));
        float eh = rintf(__fmul_rn(y2, 0.0625f));

        const float r7 = __uint_as_float(RECIP7_BITS);
        float bsh = __fmul_rn(fmaxf(__fadd_rn(__fsub_rn(eh, sh), 1.0f), 1.0f), r7);
        float bsw = __fmul_rn(fmaxf(__fadd_rn(__fsub_rn(ew, sw), 1.0f), 1.0f), r7);

        float hsf = fminf(fmaxf(__fadd_rn(floorf(__fmul_rn((float)i, bsh)), sh), 0.0f), 40.0f);
        float hef = fminf(fmaxf(__fadd_rn(ceilf(__fmul_rn((float)(i + 1), bsh)), sh), 0.0f), 40.0f);
        float wsf = fminf(fmaxf(__fadd_rn(floorf(__fmul_rn((float)j, bsw)), sw), 0.0f), 40.0f);
        float wef = fminf(fmaxf(__fadd_rn(ceilf(__fmul_rn((float)(j + 1), bsw)), sw), 0.0f), 40.0f);

        s_hs[t] = (int)hsf;
        s_he[t] = (int)hef;
        s_ws[t] = (int)wsf;
        s_we[t] = (int)wef;
    }
    __syncthreads();

    int bin = t % 49;
    int c   = blockIdx.y * CCHUNK + t / 49;

    int hs = s_hs[bin], he = s_he[bin];
    int ws = s_ws[bin], we = s_we[bin];

    float v = 0.0f;
    if (he > hs && we > ws) {
        float mmax = -1.0e30f;
        const float* fc = feat + c * (H_ * W_);
        for (int hy = hs; hy < he; ++hy) {
            const float* frow = fc + hy * W_;
            for (int wx = ws; wx < we; ++wx)
                mmax = fmaxf(mmax, __ldg(&frow[wx]));
        }
        v = mmax;
    }
    out[(b * C_ + c) * 49 + bin] = v;
}

// ---------------------------------------------------------------------------
extern "C" void kernel_launch(void* const* d_in, const int* in_sizes, int n_in,
                              void* d_out, int out_size)
{
    const float* features = (const float*)d_in[0];
    const float* rois     = (const float*)d_in[1];
    const void*  hh_p     = (n_in > 2) ? d_in[2] : nullptr;
    const void*  hw_p     = (n_in > 3) ? d_in[3] : nullptr;

    int N = in_sizes[1] / 5;              // 32
    int NB = N * 9;                       // 288
    int pool_total = NB * C_ * PH * PW;   // 3,612,672

    float* out = (float*)d_out;
    float* out_tail = (out_size >= pool_total + NB * 5) ? (out + pool_total) : nullptr;

    int threads1 = N * 8;
    anchor_kernel<<<1, threads1>>>(rois, hh_p, hw_p, out_tail, N);

    dim3 grid2(NB, C_ / CCHUNK);          // (288, 32)
    pool_kernel<<<grid2, POOL_THREADS>>>(features, out);
}

// round 13
// speedup vs baseline: 2.3780x; 1.5838x over previous
#include <cuda_runtime.h>
#include <cuda_bf16.h>

#define PH 7
#define PW 7
#define C_ 256
#define H_ 40
#define W_ 40
#define CPT 4                      // channels per thread
#define QW  8                      // channel-quads per block
#define POOL_THREADS (PH * PW * QW)   // 392
#define GRID_Y (C_ / (QW * CPT))      // 8

// f32(1/7) and f32(1/3) as XLA's constant-folded reciprocals.
#define RECIP7_BITS 0x3E124925u
#define RECIP3_BITS 0x3EAAAAABu

__constant__ int c_sel[8] = {0, 1, 2, 3, 5, 6, 7, 8};

__device__ __forceinline__ float decode_scalar(const void* p, float dflt)
{
    if (p == nullptr) return dflt;
    unsigned int lo = *(const unsigned int*)p;
    if (lo >= 1u && lo <= 1000000u) return (float)lo;   // int32/int64 low word
    float f = __uint_as_float(lo);
    if (f >= 1.0f && f <= 1.0e6f) return f;             // float32
    return dflt;
}

// ---------------------------------------------------------------------------
// Fused kernel: warp 0 of every block recomputes its box's anchor result
// (bit-exact vs the R8/R11 anchor kernel), then all 392 threads pool
// 4 channels each. grid = (288 boxes, 8 channel groups).
// ---------------------------------------------------------------------------
__global__ void __launch_bounds__(POOL_THREADS)
fused_kernel(const float* __restrict__ feat,
             const float* __restrict__ rois,
             const void* __restrict__ hh_p,
             const void* __restrict__ hw_p,
             float* __restrict__ out,
             float* __restrict__ out_tail,   // nullptr if no room
             int N)
{
    __shared__ float sbox[4];
    __shared__ int s_hs[49], s_he[49], s_ws[49], s_we[49];

    int b = blockIdx.x;
    int t = threadIdx.x;
    int n = b / 9, jj = b % 9;

    // ---------------- Phase A: per-box anchor result (warp 0) -------------
    if (t < 32) {
        int lane = t;
        float x1 = rois[n * 5 + 1], y1 = rois[n * 5 + 2];
        float x2 = rois[n * 5 + 3], y2 = rois[n * 5 + 4];
        float o0 = 0.0f, o1, o2, o3, o4;

        if (jj == 0) {
            o0 = rois[n * 5 + 0];
            o1 = x1; o2 = y1; o3 = x2; o4 = y2;
        } else {
            float fhh = decode_scalar(hh_p, 640.0f);
            float fhw = decode_scalar(hw_p, 640.0f);
            int m = c_sel[jj - 1];
            float ky = (float)(m / 3), kx = (float)(m % 3);

            float w = __fsub_rn(x2, x1), h = __fsub_rn(y2, y1);
            float cx = __fadd_rn(x1, __fmul_rn(w, __fsub_rn(kx, 0.5f)));
            float cy = __fadd_rn(y1, __fmul_rn(h, __fsub_rn(ky, 0.5f)));
            float w4 = __fmul_rn(w, 0.25f), h4 = __fmul_rn(h, 0.25f);
            float g0 = __fsub_rn(cx, w4), g1 = __fsub_rn(cy, h4);
            float g2 = __fadd_rn(cx, w4), g3 = __fadd_rn(cy, h4);
            float bw = __fadd_rn(__fsub_rn(g2, g0), 1.0f);
            float bh = __fadd_rn(__fsub_rn(g3, g1), 1.0f);
            bool invalid = (g0 < 0.0f) || (g1 < 0.0f) || (g2 >= fhw) || (g3 >= fhh)
                        || (bw < 16.0f) || (bh < 16.0f);
            if (invalid) { g0 = x1; g1 = y1; g2 = x2; g3 = y2; }

            float gwp = __fadd_rn(__fsub_rn(g2, g0), 1.0f);
            float ghp = __fadd_rn(__fsub_rn(g3, g1), 1.0f);
            float gArea = __fmul_rn(gwp, ghp);

            // Each lane handles rois a = lane, lane+32, ...
            float my_ov = -3.0e38f;
            int my_idx = 0x7fffffff;
            for (int a = lane; a < N; a += 32) {
                float a0 = rois[a * 5 + 1], a1 = rois[a * 5 + 2];
                float a2 = rois[a * 5 + 3], a3 = rois[a * 5 + 4];
                float aw = __fadd_rn(__fsub_rn(a2, a0), 1.0f);
                float ah = __fadd_rn(__fsub_rn(a3, a1), 1.0f);
                float iw = fmaxf(__fadd_rn(__fsub_rn(fminf(a2, g2), fmaxf(a0, g0)), 1.0f), 0.0f);
                float ih = fmaxf(__fadd_rn(__fsub_rn(fminf(a3, g3), fmaxf(a1, g1)), 1.0f), 0.0f);
                float inter = __fmul_rn(iw, ih);
                float uni = __fsub_rn(__fadd_rn(__fmul_rn(aw, ah), gArea), inter);
                float ov = __fdiv_rn(inter, uni);
                if (gwp == 1.0f && ghp == 1.0f) ov = 0.0f;
                if (aw == 1.0f && ah == 1.0f)   ov = -1.0f;
                if (ov > my_ov) { my_ov = ov; my_idx = a; }
            }
            // Argmax reduction, first-occurrence tie-break (lower index wins).
            #pragma unroll
            for (int off = 16; off > 0; off >>= 1) {
                float ov2 = __shfl_down_sync(0xffffffffu, my_ov, off);
                int   id2 = __shfl_down_sync(0xffffffffu, my_idx, off);
                if (ov2 > my_ov || (ov2 == my_ov && id2 < my_idx)) {
                    my_ov = ov2; my_idx = id2;
                }
            }
            my_ov  = __shfl_sync(0xffffffffu, my_ov, 0);
            my_idx = __shfl_sync(0xffffffffu, my_idx, 0);

            bool lab = (my_ov >= 0.3f);
            float w_cell = __fsub_rn(g2, g0);
            float h_cell = __fsub_rn(g3, g1);
            float rw = 0.0f, rh = 0.0f;
            if (lab) {
                rw = __fsub_rn(rois[my_idx * 5 + 3], rois[my_idx * 5 + 1]);
                rh = __fsub_rn(rois[my_idx * 5 + 4], rois[my_idx * 5 + 2]);
            }
            bool kill1 = (fmaxf(rw, rh) >= fmaxf(w_cell, h_cell));
            float third = __fmul_rn(fminf(w_cell, h_cell), __uint_as_float(RECIP3_BITS));
            bool kill2 = (fminf(rw, rh) < third);
            lab = lab && (!kill1) && (!kill2);

            if (lab) {
                o1 = rois[my_idx * 5 + 1]; o2 = rois[my_idx * 5 + 2];
                o3 = rois[my_idx * 5 + 3]; o4 = rois[my_idx * 5 + 4];
            } else {
                o1 = g0; o2 = g1; o3 = g2; o4 = g3;
            }
        }

        if (lane == 0) {
            sbox[0] = o1; sbox[1] = o2; sbox[2] = o3; sbox[3] = o4;
            if (out_tail != nullptr && blockIdx.y == 0) {
                out_tail[b * 5 + 0] = o0;
                out_tail[b * 5 + 1] = o1;
                out_tail[b * 5 + 2] = o2;
                out_tail[b * 5 + 3] = o3;
                out_tail[b * 5 + 4] = o4;
            }
        }
    }
    __syncthreads();

    // ---------------- Phase B: 49 bin windows (threads 0..48) -------------
    if (t < 49) {
        int i = t / 7, j = t % 7;

        float x1 = sbox[0], y1 = sbox[1], x2 = sbox[2], y2 = sbox[3];

        float sw = rintf(__fmul_rn(x1, 0.0625f));
        float sh = rintf(__fmul_rn(y1, 0.0625f));
        float ew = rintf(__fmul_rn(x2, 0.0625f));
        float eh = rintf(__fmul_rn(y2, 0.0625f));

        const float r7 = __uint_as_float(RECIP7_BITS);
        float bsh = __fmul_rn(fmaxf(__fadd_rn(__fsub_rn(eh, sh), 1.0f), 1.0f), r7);
        float bsw = __fmul_rn(fmaxf(__fadd_rn(__fsub_rn(ew, sw), 1.0f), 1.0f), r7);

        float hsf = fminf(fmaxf(__fadd_rn(floorf(__fmul_rn((float)i, bsh)), sh), 0.0f), 40.0f);
        float hef = fminf(fmaxf(__fadd_rn(ceilf(__fmul_rn((float)(i + 1), bsh)), sh), 0.0f), 40.0f);
        float wsf = fminf(fmaxf(__fadd_rn(floorf(__fmul_rn((float)j, bsw)), sw), 0.0f), 40.0f);
        float wef = fminf(fmaxf(__fadd_rn(ceilf(__fmul_rn((float)(j + 1), bsw)), sw), 0.0f), 40.0f);

        s_hs[t] = (int)hsf;
        s_he[t] = (int)hef;
        s_ws[t] = (int)wsf;
        s_we[t] = (int)wef;
    }
    __syncthreads();

    // ---------------- Phase C: pool 4 channels per thread -----------------
    int bin = t % 49;
    int q   = t / 49;                       // 0..7
    int c0  = blockIdx.y * (QW * CPT) + q * CPT;

    int hs = s_hs[bin], he = s_he[bin];
    int ws = s_ws[bin], we = s_we[bin];

    const float* f0 = feat + (c0 + 0) * (H_ * W_);
    const float* f1 = feat + (c0 + 1) * (H_ * W_);
    const float* f2 = feat + (c0 + 2) * (H_ * W_);
    const float* f3 = feat + (c0 + 3) * (H_ * W_);

    float v0 = 0.0f, v1 = 0.0f, v2 = 0.0f, v3 = 0.0f;
    if (he > hs && we > ws) {
        float m0 = -1.0e30f, m1 = -1.0e30f, m2 = -1.0e30f, m3 = -1.0e30f;
        for (int hy = hs; hy < he; ++hy) {
            int base = hy * W_;
            for (int wx = ws; wx < we; ++wx) {
                int o = base + wx;
                m0 = fmaxf(m0, __ldg(f0 + o));
                m1 = fmaxf(m1, __ldg(f1 + o));
                m2 = fmaxf(m2, __ldg(f2 + o));
                m3 = fmaxf(m3, __ldg(f3 + o));
            }
        }
        v0 = m0; v1 = m1; v2 = m2; v3 = m3;
    }

    float* ob = out + ((size_t)b * C_ + c0) * 49 + bin;
    ob[0 * 49] = v0;
    ob[1 * 49] = v1;
    ob[2 * 49] = v2;
    ob[3 * 49] = v3;
}

// ---------------------------------------------------------------------------
extern "C" void kernel_launch(void* const* d_in, const int* in_sizes, int n_in,
                              void* d_out, int out_size)
{
    const float* features = (const float*)d_in[0];
    const float* rois     = (const float*)d_in[1];
    const void*  hh_p     = (n_in > 2) ? d_in[2] : nullptr;
    const void*  hw_p     = (n_in > 3) ? d_in[3] : nullptr;

    int N = in_sizes[1] / 5;              // 32
    int NB = N * 9;                       // 288
    int pool_total = NB * C_ * PH * PW;   // 3,612,672

    float* out = (float*)d_out;
    float* out_tail = (out_size >= pool_total + NB * 5) ? (out + pool_total) : nullptr;

    dim3 grid(NB, GRID_Y);                // (288, 8)
    fused_kernel<<<grid, POOL_THREADS>>>(features, rois, hh_p, hw_p,
                                         out, out_tail, N);
}